// round 14
// baseline (speedup 1.0000x reference)
#include <cuda_runtime.h>
#include <cuda_bf16.h>
#include <math.h>
#include <stdint.h>

#define BB 4
#define HH 128
#define WW 128
#define CC 768
#define WF 65            // WW/2 + 1
#define NB 8
#define PI_D 3.14159265358979323846

// Spectrum scratch, interleaved complex, layout [B, kw, H, C] (~204MB)
#define NSPEC (BB * WF * HH * CC)
__device__ float2 g_Y[NSPEC];

// Chunk-major bf16 weight images:
// [2 layers][8 n][2 parts(hi/lo)][4 chunks][192 rows][56 cols(48 used)]
#define BROW 56
#define CHUNK_ELEM (192 * BROW)           // 10752 elems = 21504 B
__device__ __align__(16) __nv_bfloat16 g_Wt[2 * 8 * 2 * 4 * CHUNK_ELEM];

__device__ __forceinline__ float gelu_exact(float x) {
    return 0.5f * x * (1.0f + erff(x * 0.7071067811865476f));
}
__device__ __forceinline__ float sshrink(float v) {
    float a = fabsf(v) - 0.01f;
    return a > 0.0f ? copysignf(a, v) : 0.0f;
}
__device__ __forceinline__ uint32_t pack_bf2(float a, float b) {
    __nv_bfloat162 p = make_bfloat162(__float2bfloat16(a), __float2bfloat16(b));
    return *(uint32_t*)&p;
}
__device__ __forceinline__ float lo_part(float v) {
    return v - __bfloat162float(__float2bfloat16(v));
}
__device__ __forceinline__ uint32_t smem_u32(const void* p) {
    uint32_t a;
    asm("{ .reg .u64 t; cvta.to.shared.u64 t, %1; cvt.u32.u64 %0, t; }"
        : "=r"(a) : "l"(p));
    return a;
}
__device__ __forceinline__ void cp16(uint32_t dst, const void* src) {
    asm volatile("cp.async.cg.shared.global [%0], [%1], 16;" :: "r"(dst), "l"(src));
}
__device__ __forceinline__ void cp_commit() {
    asm volatile("cp.async.commit_group;" ::: "memory");
}
__device__ __forceinline__ void cp_wait0() {
    asm volatile("cp.async.wait_group 0;" ::: "memory");
}
__device__ __forceinline__ void ldsm4(uint32_t& r0, uint32_t& r1,
                                      uint32_t& r2, uint32_t& r3, uint32_t addr) {
    asm volatile("ldmatrix.sync.aligned.m8n8.x4.shared.b16 {%0,%1,%2,%3}, [%4];"
                 : "=r"(r0), "=r"(r1), "=r"(r2), "=r"(r3) : "r"(addr));
}
__device__ __forceinline__ void mma16816(float* c, const uint32_t* a,
                                         uint32_t b0, uint32_t b1) {
    asm volatile(
        "mma.sync.aligned.m16n8k16.row.col.f32.bf16.bf16.f32 "
        "{%0,%1,%2,%3}, {%4,%5,%6,%7}, {%8,%9}, {%0,%1,%2,%3};"
        : "+f"(c[0]), "+f"(c[1]), "+f"(c[2]), "+f"(c[3])
        : "r"(a[0]), "r"(a[1]), "r"(a[2]), "r"(a[3]), "r"(b0), "r"(b1));
}

// ===========================================================================
// K0: weight prep -> chunk-major layout. (unchanged)
// ===========================================================================
__global__ __launch_bounds__(256) void k_prep(const float* __restrict__ w1,
                                              const float* __restrict__ w2) {
    int gid = blockIdx.x * 256 + threadIdx.x;
    if (gid >= 2 * 8 * 2 * 4 * CHUNK_ELEM) return;
    int kc = gid % BROW;
    int nn = (gid / BROW) % 192;
    int ck = (gid / CHUNK_ELEM) % 4;
    int part = (gid / (CHUNK_ELEM * 4)) % 2;
    int n = (gid / (CHUNK_ELEM * 8)) % 8;
    int l = gid / (CHUNK_ELEM * 64);
    float v = 0.f;
    if (kc < 48) {
        int k = ck * 48 + kc;
        const float* W = l ? w2 : w1;
        int i = k >> 1, odd = k & 1;
        if (nn < 96) {
            v = odd ? -W[73728 + n * 9216 + i * 96 + nn]
                    :  W[n * 9216 + i * 96 + nn];
        } else {
            int o = nn - 96;
            v = odd ? W[n * 9216 + i * 96 + o]
                    : W[73728 + n * 9216 + i * 96 + o];
        }
    }
    if (part) v = lo_part(v);
    g_Wt[gid] = __float2bfloat16(v);
}

// ===========================================================================
// K-FUSED: forward H-FFT + block-MLP(2 layers) + inverse H-FFT, one CTA per
// (b, kw, n). 384 threads (12 warps: 4 wm x 3 wn). IN PLACE on g_Y.
// smem: sy/A union | B double buffer | bias | twiddles.
// ===========================================================================
#define WROW 200
#define SY_OFF   0           // 128*96*8 = 98304 (A union extends to 102400)
#define AH_OFF   0
#define AL_OFF   51200
#define B_OFF    102400      // 2 * 21504
#define BIAS_OFF 145408      // 384 floats
#define TWF_OFF  146944      // 128 float2
#define TWI_OFF  147968      // 128 float2
#define T16F_OFF 148992      // 16 float2
#define T16I_OFF 149120      // 16 float2
#define SMEM_FUSED 149504

__global__ __launch_bounds__(384, 1) void k_fused(const float* __restrict__ b1,
                                                  const float* __restrict__ b2) {
    extern __shared__ __align__(16) char smem[];
    const int t = threadIdx.x;
    const int wid = t >> 5, lane = t & 31;
    const int l4 = lane >> 2, qq = lane & 3;
    const int wm = wid & 3, wn = wid >> 2;          // 4 x 3
    const int bkw = blockIdx.x;                      // b*WF + kw
    const int n = blockIdx.y;
    const int cb = n * 96;
    const size_t base = ((size_t)bkw * HH) * CC + cb;    // g_Y column base
    const uint32_t sb = smem_u32(smem);

    float2* sy = (float2*)(smem + SY_OFF);
    float* sbias = (float*)(smem + BIAS_OFF);
    float2* twf = (float2*)(smem + TWF_OFF);
    float2* twi = (float2*)(smem + TWI_OFF);
    float2* t16f = (float2*)(smem + T16F_OFF);
    float2* t16i = (float2*)(smem + T16I_OFF);

    // ---- prologue: issue B chunk0 + sy column loads via cp.async ----
    {
        const char* src = (const char*)(g_Wt + (size_t)n * 2 * 4 * CHUNK_ELEM);
        for (int v = t; v < 1344; v += 384) cp16(sb + B_OFF + v * 16, src + v * 16);
        cp_commit();
    }
    for (int v = t; v < 6144; v += 384) {           // 128h x 96c x 8B
        int h = v / 48, c2 = (v % 48) * 2;
        cp16(sb + SY_OFF + (h * 96 + c2) * 8,
             (const char*)(g_Y + base + (size_t)h * CC + c2));
    }
    cp_commit();

    if (t < 96) {
        sbias[t]       = b1[cb + t];
        sbias[96 + t]  = b1[768 + cb + t];
        sbias[192 + t] = b2[cb + t];
        sbias[288 + t] = b2[768 + cb + t];
    }
    if (t < 128) {
        double a = 2.0 * PI_D * (double)t / 128.0;
        float ca = (float)cos(a), sa = (float)sin(a);
        twf[t] = make_float2(ca, -sa);
        twi[t] = make_float2(ca, sa);
    }
    if (t < 16) {
        double a = 2.0 * PI_D * (double)t / 16.0;
        float ca = (float)cos(a), sa = (float)sin(a);
        t16f[t] = make_float2(ca, -sa);
        t16i[t] = make_float2(ca, sa);
    }
    cp_wait0();
    __syncthreads();

    const int cl = t & 31;
    const int kq = (t >> 5) & 7;     // class for FFT phases (threads 256+ unused)
    const bool fft_act = (t < 256);

    // ---- forward H-FFT Stage A (16-pt DFT over h1), in place in sy ----
    if (fft_act) {
        #pragma unroll 1
        for (int cc = 0; cc < 3; cc++) {
            const int ch = cl + 32 * cc;
            float2 yv[16];
            #pragma unroll
            for (int h1 = 0; h1 < 16; h1++) yv[h1] = sy[((h1 << 3) + kq) * 96 + ch];
            #pragma unroll
            for (int m = 0; m < 8; m++) {
                float2 E = make_float2(0.f, 0.f), O = make_float2(0.f, 0.f);
                int ph = 0; const int st = (2 * m) & 15;
                #pragma unroll
                for (int u = 0; u < 8; u++) {
                    float2 tt = t16f[ph];
                    float2 a = yv[2 * u], bv = yv[2 * u + 1];
                    E.x += a.x * tt.x - a.y * tt.y;   E.y += a.x * tt.y + a.y * tt.x;
                    O.x += bv.x * tt.x - bv.y * tt.y; O.y += bv.x * tt.y + bv.y * tt.x;
                    ph = (ph + st) & 15;
                }
                float2 wm2 = t16f[m];
                float wOx = wm2.x * O.x - wm2.y * O.y;
                float wOy = wm2.x * O.y + wm2.y * O.x;
                sy[((m << 3) + kq) * 96 + ch]       = make_float2(E.x + wOx, E.y + wOy);
                sy[(((m + 8) << 3) + kq) * 96 + ch] = make_float2(E.x - wOx, E.y - wOy);
            }
        }
    }
    __syncthreads();

    // ---- forward Stage B -> registers (scale 1/128) ----
    float Xc[8][3][4];               // [j][cc][{r_k, i_k, r_k64, i_k64}]
    if (fft_act) {
        const float s = 1.0f / 128.0f;
        #pragma unroll 1
        for (int j = 0; j < 8; j++) {
            const int k = kq + 8 * j;
            const int k0 = k & 15;
            #pragma unroll
            for (int cc = 0; cc < 3; cc++) {
                const int ch = cl + 32 * cc;
                float Ex = 0.f, Ey = 0.f, Ox = 0.f, Oy = 0.f;
                int ph = 0;
                #pragma unroll
                for (int p = 0; p < 8; p++) {
                    float2 tt = twf[ph];
                    float2 g = sy[((k0 << 3) + p) * 96 + ch];
                    float rx = g.x * tt.x - g.y * tt.y;
                    float ry = g.x * tt.y + g.y * tt.x;
                    if ((p & 1) == 0) { Ex += rx; Ey += ry; }
                    else              { Ox += rx; Oy += ry; }
                    ph = (ph + k) & 127;
                }
                Xc[j][cc][0] = (Ex + Ox) * s;  Xc[j][cc][1] = (Ey + Oy) * s;
                Xc[j][cc][2] = (Ex - Ox) * s;  Xc[j][cc][3] = (Ey - Oy) * s;
            }
        }
    }
    __syncthreads();                 // all sy reads done; safe to overwrite as A

    // ---- write A image (bf16 hi/lo, k-interleaved re/im) ----
    if (fft_act) {
        #pragma unroll 1
        for (int j = 0; j < 8; j++) {
            const int k = kq + 8 * j;
            #pragma unroll
            for (int cc = 0; cc < 3; cc++) {
                const int i = cl + 32 * cc;
                float r0 = Xc[j][cc][0], i0 = Xc[j][cc][1];
                float r1 = Xc[j][cc][2], i1 = Xc[j][cc][3];
                *(uint32_t*)(smem + AH_OFF + (k * WROW + 2 * i) * 2) = pack_bf2(r0, i0);
                *(uint32_t*)(smem + AL_OFF + (k * WROW + 2 * i) * 2) =
                    pack_bf2(lo_part(r0), lo_part(i0));
                *(uint32_t*)(smem + AH_OFF + ((k + 64) * WROW + 2 * i) * 2) = pack_bf2(r1, i1);
                *(uint32_t*)(smem + AL_OFF + ((k + 64) * WROW + 2 * i) * 2) =
                    pack_bf2(lo_part(r1), lo_part(i1));
            }
        }
    }

    // ---- MLP: 16-chunk double-buffered schedule (layers 0,1) ----
    float c[2][8][4];
    #pragma unroll
    for (int mf = 0; mf < 2; mf++)
        #pragma unroll
        for (int nf = 0; nf < 8; nf++)
            #pragma unroll
            for (int e = 0; e < 4; e++) c[mf][nf][e] = 0.f;

    const int rb = 32 * wm;
    const int nbase = 64 * wn;

    const int arow = rb + (lane & 7) + ((lane & 8) ? 8 : 0);
    const int acol = (lane & 16) ? 8 : 0;
    uint32_t aAddrH[2], aAddrL[2];
    #pragma unroll
    for (int mf = 0; mf < 2; mf++) {
        aAddrH[mf] = sb + AH_OFF + ((arow + 16 * mf) * WROW + acol) * 2;
        aAddrL[mf] = sb + AL_OFF + ((arow + 16 * mf) * WROW + acol) * 2;
    }
    const int brow = (lane & 7) + ((lane & 16) ? 8 : 0);
    const int bcol = (lane & 8) ? 8 : 0;
    uint32_t bAddr[4];
    #pragma unroll
    for (int bf = 0; bf < 4; bf++)
        bAddr[bf] = sb + B_OFF + ((nbase + 16 * bf + brow) * BROW + bcol) * 2;

    #pragma unroll 1
    for (int cid = 0; cid < 16; cid++) {
        cp_wait0();
        __syncthreads();
        if (cid < 15) {
            int nx = cid + 1;
            int l = nx >> 3, part = (nx >> 2) & 1, ck = nx & 3;
            const char* src = (const char*)(g_Wt +
                ((size_t)((l * 8 + n) * 2 + part) * 4 + ck) * CHUNK_ELEM);
            uint32_t dst = sb + B_OFF + (nx & 1) * 21504;
            #pragma unroll 1
            for (int v = t; v < 1344; v += 384) cp16(dst + v * 16, src + v * 16);
            cp_commit();
        }
        if (cid == 8) {
            // epilogue 1: bias + GELU, rewrite A hi/lo, reset accum
            #pragma unroll
            for (int mf = 0; mf < 2; mf++) {
                const int r0 = rb + 16 * mf + l4;
                #pragma unroll
                for (int nf = 0; nf < 8; nf++) {
                    const int n0 = nbase + 8 * nf + 2 * qq;
                    #pragma unroll
                    for (int e = 0; e < 4; e++) {
                        const int nc = n0 + (e & 1);
                        const int r = (e < 2) ? r0 : r0 + 8;
                        const int kk = (nc < 96) ? 2 * nc : 2 * (nc - 96) + 1;
                        float g = gelu_exact(c[mf][nf][e] + sbias[nc]);
                        *(__nv_bfloat16*)(smem + AH_OFF + (r * WROW + kk) * 2) =
                            __float2bfloat16(g);
                        *(__nv_bfloat16*)(smem + AL_OFF + (r * WROW + kk) * 2) =
                            __float2bfloat16(lo_part(g));
                        c[mf][nf][e] = 0.f;
                    }
                }
            }
            __syncthreads();
        }
        // compute chunk cid
        {
            const int part = (cid >> 2) & 1;
            const int ck = cid & 3;
            const uint32_t boff = (cid & 1) * 21504;
            #pragma unroll
            for (int ksl = 0; ksl < 3; ksl++) {
                const int kl = ksl * 16;
                const uint32_t kg2 = (ck * 48 + kl) * 2;
                uint32_t ah[2][4], al[2][4];
                ldsm4(ah[0][0], ah[0][1], ah[0][2], ah[0][3], aAddrH[0] + kg2);
                ldsm4(ah[1][0], ah[1][1], ah[1][2], ah[1][3], aAddrH[1] + kg2);
                if (part == 0) {
                    ldsm4(al[0][0], al[0][1], al[0][2], al[0][3], aAddrL[0] + kg2);
                    ldsm4(al[1][0], al[1][1], al[1][2], al[1][3], aAddrL[1] + kg2);
                }
                #pragma unroll
                for (int bf = 0; bf < 4; bf++) {
                    uint32_t b0a, b1a, b0b, b1b;
                    ldsm4(b0a, b1a, b0b, b1b, bAddr[bf] + boff + kl * 2);
                    mma16816(c[0][2 * bf],     ah[0], b0a, b1a);
                    mma16816(c[1][2 * bf],     ah[1], b0a, b1a);
                    mma16816(c[0][2 * bf + 1], ah[0], b0b, b1b);
                    mma16816(c[1][2 * bf + 1], ah[1], b0b, b1b);
                    if (part == 0) {
                        mma16816(c[0][2 * bf],     al[0], b0a, b1a);
                        mma16816(c[1][2 * bf],     al[1], b0a, b1a);
                        mma16816(c[0][2 * bf + 1], al[0], b0b, b1b);
                        mma16816(c[1][2 * bf + 1], al[1], b0b, b1b);
                    }
                }
            }
        }
    }

    // ---- epilogue 2: bias + softshrink -> sy (float2) ----
    __syncthreads();                 // A image dead everywhere
    {
        float* syf = (float*)(smem + SY_OFF);
        #pragma unroll
        for (int mf = 0; mf < 2; mf++) {
            const int r0 = rb + 16 * mf + l4;
            #pragma unroll
            for (int nf = 0; nf < 8; nf++) {
                const int n0 = nbase + 8 * nf + 2 * qq;
                #pragma unroll
                for (int e = 0; e < 4; e++) {
                    const int nc = n0 + (e & 1);
                    const int r = (e < 2) ? r0 : r0 + 8;
                    float v = sshrink(c[mf][nf][e] + sbias[192 + nc]);
                    const int cch = (nc < 96) ? nc : nc - 96;
                    syf[(r * 96 + cch) * 2 + (nc >= 96)] = v;
                }
            }
        }
    }
    __syncthreads();

    // ---- inverse H-FFT Stage A, in place in sy ----
    if (fft_act) {
        #pragma unroll 1
        for (int cc = 0; cc < 3; cc++) {
            const int ch = cl + 32 * cc;
            float2 yv[16];
            #pragma unroll
            for (int h1 = 0; h1 < 16; h1++) yv[h1] = sy[((h1 << 3) + kq) * 96 + ch];
            #pragma unroll
            for (int m = 0; m < 8; m++) {
                float2 E = make_float2(0.f, 0.f), O = make_float2(0.f, 0.f);
                int ph = 0; const int st = (2 * m) & 15;
                #pragma unroll
                for (int u = 0; u < 8; u++) {
                    float2 tt = t16i[ph];
                    float2 a = yv[2 * u], bv = yv[2 * u + 1];
                    E.x += a.x * tt.x - a.y * tt.y;   E.y += a.x * tt.y + a.y * tt.x;
                    O.x += bv.x * tt.x - bv.y * tt.y; O.y += bv.x * tt.y + bv.y * tt.x;
                    ph = (ph + st) & 15;
                }
                float2 wm2 = t16i[m];
                float wOx = wm2.x * O.x - wm2.y * O.y;
                float wOy = wm2.x * O.y + wm2.y * O.x;
                sy[((m << 3) + kq) * 96 + ch]       = make_float2(E.x + wOx, E.y + wOy);
                sy[(((m + 8) << 3) + kq) * 96 + ch] = make_float2(E.x - wOx, E.y - wOy);
            }
        }
    }
    __syncthreads();

    // ---- inverse Stage B -> g_Y (scale 1) ----
    if (fft_act) {
        #pragma unroll 1
        for (int j = 0; j < 8; j++) {
            const int k = kq + 8 * j;
            const int k0 = k & 15;
            #pragma unroll
            for (int cc = 0; cc < 3; cc++) {
                const int ch = cl + 32 * cc;
                float Ex = 0.f, Ey = 0.f, Ox = 0.f, Oy = 0.f;
                int ph = 0;
                #pragma unroll
                for (int p = 0; p < 8; p++) {
                    float2 tt = twi[ph];
                    float2 g = sy[((k0 << 3) + p) * 96 + ch];
                    float rx = g.x * tt.x - g.y * tt.y;
                    float ry = g.x * tt.y + g.y * tt.x;
                    if ((p & 1) == 0) { Ex += rx; Ey += ry; }
                    else              { Ox += rx; Oy += ry; }
                    ph = (ph + k) & 127;
                }
                g_Y[base + (size_t)k * CC + ch] = make_float2(Ex + Ox, Ey + Oy);
                g_Y[base + (size_t)(k + 64) * CC + ch] = make_float2(Ex - Ox, Ey - Oy);
            }
        }
    }
}

// ===========================================================================
// K1: real FFT along W (four-step), 64 ch/CTA. (R13 version)
// ===========================================================================
__global__ __launch_bounds__(256, 4) void k_rfft_w(const float* __restrict__ x) {
    extern __shared__ __align__(16) float sm1[];
    float* sx = sm1;
    float* sg8 = sx + 8192;
    float2* tw = (float2*)(sg8 + 512);
    float2* tw16 = tw + 128;

    const int t = threadIdx.x;
    const int bh = blockIdx.x;
    const int b = bh >> 7, h = bh & 127;
    const int cb = blockIdx.y * 64;
    const uint32_t sbx = smem_u32(sm1);

    const float* xp = x + (size_t)bh * WW * CC + cb;
    for (int v = t; v < 2048; v += 256) {
        int w = v >> 4, c4 = v & 15;
        cp16(sbx + (w * 64 + c4 * 4) * 4, xp + (size_t)w * CC + c4 * 4);
    }
    cp_commit();
    if (t < 128) {
        double a = -2.0 * PI_D * (double)t / 128.0;
        tw[t] = make_float2((float)cos(a), (float)sin(a));
    }
    if (t < 16) {
        double a = -2.0 * PI_D * (double)t / 16.0;
        tw16[t] = make_float2((float)cos(a), (float)sin(a));
    }
    cp_wait0();
    __syncthreads();

    const int cl = t & 31;
    const int w0 = t >> 5;

    #pragma unroll
    for (int cc = 0; cc < 2; cc++) {
        const int ch = cl + 32 * cc;
        float xv[16];
        #pragma unroll
        for (int w1 = 0; w1 < 16; w1++) xv[w1] = sx[((w1 << 3) + w0) * 64 + ch];
        #pragma unroll
        for (int m = 0; m < 8; m++) {
            float2 E = make_float2(0.f, 0.f), O = make_float2(0.f, 0.f);
            int ph = 0; const int st = (2 * m) & 15;
            #pragma unroll
            for (int u = 0; u < 8; u++) {
                float2 tt = tw16[ph];
                E.x += xv[2 * u] * tt.x;     E.y += xv[2 * u] * tt.y;
                O.x += xv[2 * u + 1] * tt.x; O.y += xv[2 * u + 1] * tt.y;
                ph = (ph + st) & 15;
            }
            if (m == 0) sg8[w0 * 64 + ch] = E.x - O.x;
            float2 wm = tw16[m];
            float wOx = wm.x * O.x - wm.y * O.y;
            float wOy = wm.x * O.y + wm.y * O.x;
            sx[((m << 3) + w0) * 64 + ch]       = E.x + wOx;
            sx[(((m + 8) << 3) + w0) * 64 + ch] = E.y + wOy;
        }
    }
    __syncthreads();

    const int kq = w0;
    float2* yout = g_Y + ((size_t)b * WF * HH + h) * CC + cb;
    const size_t sk = (size_t)HH * CC;
    const int jmax = (kq == 0) ? 9 : 8;
    for (int j = 0; j < jmax; j++) {
        const int k = kq + 8 * j;
        const int k0 = k & 15;
        const bool is8 = (k0 == 8);
        const int k0p = (k0 <= 8) ? k0 : 16 - k0;
        const float si = (k0 <= 8) ? 1.f : -1.f;
        #pragma unroll
        for (int cc = 0; cc < 2; cc++) {
            const int ch = cl + 32 * cc;
            float ax = 0.f, ay = 0.f;
            int ph = 0;
            #pragma unroll
            for (int p = 0; p < 8; p++) {
                float2 tt = tw[ph];
                float gre, gim;
                if (is8) { gre = sg8[p * 64 + ch]; gim = 0.f; }
                else {
                    gre = sx[((k0p << 3) + p) * 64 + ch];
                    gim = si * sx[(((k0p + 8) << 3) + p) * 64 + ch];
                }
                ax += gre * tt.x - gim * tt.y;
                ay += gre * tt.y + gim * tt.x;
                ph = (ph + k) & 127;
            }
            yout[(size_t)k * sk + ch] = make_float2(ax, ay);
        }
    }
}

// ===========================================================================
// K5: inverse real FFT along W (four-step), 64 ch/CTA. (R13 version)
// ===========================================================================
__global__ __launch_bounds__(256, 3) void k_irfft_w(float* __restrict__ out) {
    extern __shared__ __align__(16) float sm5[];
    float2* sz = (float2*)sm5;
    float2* tw = sz + 8192;
    float2* tw16 = tw + 128;

    const int t = threadIdx.x;
    const int bh = blockIdx.x;
    const int b = bh >> 7, h = bh & 127;
    const int cb = blockIdx.y * 64;
    const size_t base = ((size_t)b * WF * HH + h) * CC + cb;
    const size_t sk = (size_t)HH * CC;
    const uint32_t sbZ = smem_u32(sm5);

    for (int v = t; v < 2080; v += 256) {
        int k = v >> 5, c2 = (v & 31) * 2;
        cp16(sbZ + (k * 64 + c2) * 8, (const char*)(g_Y + base + (size_t)k * sk + c2));
    }
    cp_commit();
    if (t < 128) {
        double a = 2.0 * PI_D * (double)t / 128.0;
        tw[t] = make_float2((float)cos(a), (float)sin(a));
    }
    if (t < 16) {
        double a = 2.0 * PI_D * (double)t / 16.0;
        tw16[t] = make_float2((float)cos(a), (float)sin(a));
    }
    cp_wait0();
    __syncthreads();
    for (int idx = t; idx < 63 * 64; idx += 256) {
        int k = 65 + (idx >> 6), c = idx & 63;
        float2 v2 = sz[((128 - k) << 6) + c];
        sz[(k << 6) + c] = make_float2(v2.x, -v2.y);
    }
    __syncthreads();

    const int cl = t & 31;
    const int k0c = t >> 5;

    #pragma unroll
    for (int cc = 0; cc < 2; cc++) {
        const int ch = cl + 32 * cc;
        float2 yv[16];
        #pragma unroll
        for (int k1 = 0; k1 < 16; k1++) yv[k1] = sz[((k1 << 3) + k0c) * 64 + ch];
        #pragma unroll
        for (int m = 0; m < 8; m++) {
            float2 E = make_float2(0.f, 0.f), O = make_float2(0.f, 0.f);
            int ph = 0; const int st = (2 * m) & 15;
            #pragma unroll
            for (int u = 0; u < 8; u++) {
                float2 tt = tw16[ph];
                float2 a = yv[2 * u], bv = yv[2 * u + 1];
                E.x += a.x * tt.x - a.y * tt.y;   E.y += a.x * tt.y + a.y * tt.x;
                O.x += bv.x * tt.x - bv.y * tt.y; O.y += bv.x * tt.y + bv.y * tt.x;
                ph = (ph + st) & 15;
            }
            float2 wm = tw16[m];
            float wOx = wm.x * O.x - wm.y * O.y;
            float wOy = wm.x * O.y + wm.y * O.x;
            sz[((m << 3) + k0c) * 64 + ch]       = make_float2(E.x + wOx, E.y + wOy);
            sz[(((m + 8) << 3) + k0c) * 64 + ch] = make_float2(E.x - wOx, E.y - wOy);
        }
    }
    __syncthreads();

    const int wq = k0c;
    const float inv = 1.0f / 128.0f;
    float* op = out + (size_t)bh * WW * CC + cb;
    #pragma unroll 2
    for (int j = 0; j < 8; j++) {
        const int w = wq + 8 * j;
        const int m = w & 15;
        #pragma unroll
        for (int cc = 0; cc < 2; cc++) {
            const int ch = cl + 32 * cc;
            float e = 0.f, o = 0.f;
            int ph = 0;
            #pragma unroll
            for (int p = 0; p < 8; p++) {
                float2 tt = tw[ph];
                float2 g = sz[((m << 3) + p) * 64 + ch];
                float re = g.x * tt.x - g.y * tt.y;
                if ((p & 1) == 0) e += re; else o += re;
                ph = (ph + w) & 127;
            }
            op[(size_t)w * CC + ch]        = (e + o) * inv;
            op[(size_t)(w + 64) * CC + ch] = (e - o) * inv;
        }
    }
}

// ---------------------------------------------------------------------------
extern "C" void kernel_launch(void* const* d_in, const int* in_sizes, int n_in,
                              void* d_out, int out_size) {
    const float* x  = (const float*)d_in[0];
    const float* w1 = (const float*)d_in[1];
    const float* b1 = (const float*)d_in[2];
    const float* w2 = (const float*)d_in[3];
    const float* b2 = (const float*)d_in[4];
    float* out = (float*)d_out;

    const int smem_rfft  = 8192 * 4 + 512 * 4 + 128 * 8 + 16 * 8;
    const int smem_irfft = 8192 * 8 + 128 * 8 + 16 * 8;
    cudaFuncSetAttribute(k_rfft_w,  cudaFuncAttributeMaxDynamicSharedMemorySize, smem_rfft);
    cudaFuncSetAttribute(k_fused,   cudaFuncAttributeMaxDynamicSharedMemorySize, SMEM_FUSED);
    cudaFuncSetAttribute(k_irfft_w, cudaFuncAttributeMaxDynamicSharedMemorySize, smem_irfft);

    k_prep<<<5376, 256>>>(w1, w2);

    dim3 g1(BB * HH, CC / 64);           // (512, 12)
    k_rfft_w<<<g1, 256, smem_rfft>>>(x);

    dim3 gF(BB * WF, NB);                // (260, 8)
    k_fused<<<gF, 384, SMEM_FUSED>>>(b1, b2);

    k_irfft_w<<<g1, 256, smem_irfft>>>(out);
}

// round 15
// speedup vs baseline: 1.0430x; 1.0430x over previous
#include <cuda_runtime.h>
#include <cuda_bf16.h>
#include <math.h>
#include <stdint.h>

#define BB 4
#define HH 128
#define WW 128
#define CC 768
#define WF 65            // WW/2 + 1
#define NB 8
#define PI_D 3.14159265358979323846

// Spectrum scratch, interleaved complex, layout [B, kw, H, C] (~204MB)
#define NSPEC (BB * WF * HH * CC)
__device__ float2 g_Y[NSPEC];

// Chunk-major bf16 weight images:
// [2 layers][8 n][2 parts(hi/lo)][4 chunks][192 rows][56 cols(48 used)]
#define BROW 56
#define CHUNK_ELEM (192 * BROW)           // 10752 elems = 21504 B
#define NPREP (2 * 8 * 2 * 4 * CHUNK_ELEM)
__device__ __align__(16) __nv_bfloat16 g_Wt[NPREP];

__device__ __forceinline__ float gelu_exact(float x) {
    return 0.5f * x * (1.0f + erff(x * 0.7071067811865476f));
}
__device__ __forceinline__ float sshrink(float v) {
    float a = fabsf(v) - 0.01f;
    return a > 0.0f ? copysignf(a, v) : 0.0f;
}
__device__ __forceinline__ uint32_t pack_bf2(float a, float b) {
    __nv_bfloat162 p = make_bfloat162(__float2bfloat16(a), __float2bfloat16(b));
    return *(uint32_t*)&p;
}
__device__ __forceinline__ float lo_part(float v) {
    return v - __bfloat162float(__float2bfloat16(v));
}
__device__ __forceinline__ uint32_t smem_u32(const void* p) {
    uint32_t a;
    asm("{ .reg .u64 t; cvta.to.shared.u64 t, %1; cvt.u32.u64 %0, t; }"
        : "=r"(a) : "l"(p));
    return a;
}
__device__ __forceinline__ void cp16(uint32_t dst, const void* src) {
    asm volatile("cp.async.cg.shared.global [%0], [%1], 16;" :: "r"(dst), "l"(src));
}
__device__ __forceinline__ void cp_commit() {
    asm volatile("cp.async.commit_group;" ::: "memory");
}
__device__ __forceinline__ void cp_wait0() {
    asm volatile("cp.async.wait_group 0;" ::: "memory");
}
__device__ __forceinline__ void ldsm4(uint32_t& r0, uint32_t& r1,
                                      uint32_t& r2, uint32_t& r3, uint32_t addr) {
    asm volatile("ldmatrix.sync.aligned.m8n8.x4.shared.b16 {%0,%1,%2,%3}, [%4];"
                 : "=r"(r0), "=r"(r1), "=r"(r2), "=r"(r3) : "r"(addr));
}

// m16n8k16 row.col bf16 -> f32 accumulate
__device__ __forceinline__ void mma16816(float* c, const uint32_t* a,
                                         uint32_t b0, uint32_t b1) {
    asm volatile(
        "mma.sync.aligned.m16n8k16.row.col.f32.bf16.bf16.f32 "
        "{%0,%1,%2,%3}, {%4,%5,%6,%7}, {%8,%9}, {%0,%1,%2,%3};"
        : "+f"(c[0]), "+f"(c[1]), "+f"(c[2]), "+f"(c[3])
        : "r"(a[0]), "r"(a[1]), "r"(a[2]), "r"(a[3]), "r"(b0), "r"(b1));
}

// prep one weight element (called from k_rfft_w)
__device__ __forceinline__ void prep_one(int gid, const float* __restrict__ w1,
                                         const float* __restrict__ w2) {
    int kc = gid % BROW;
    int nn = (gid / BROW) % 192;
    int ck = (gid / CHUNK_ELEM) % 4;
    int part = (gid / (CHUNK_ELEM * 4)) % 2;
    int n = (gid / (CHUNK_ELEM * 8)) % 8;
    int l = gid / (CHUNK_ELEM * 64);
    float v = 0.f;
    if (kc < 48) {
        int k = ck * 48 + kc;
        const float* W = l ? w2 : w1;
        int i = k >> 1, odd = k & 1;
        if (nn < 96) {
            v = odd ? -W[73728 + n * 9216 + i * 96 + nn]
                    :  W[n * 9216 + i * 96 + nn];
        } else {
            int o = nn - 96;
            v = odd ? W[n * 9216 + i * 96 + o]
                    : W[73728 + n * 9216 + i * 96 + o];
        }
    }
    if (part) v = lo_part(v);
    g_Wt[gid] = __float2bfloat16(v);
}

// ===========================================================================
// K3: warp-MMA complex MLP (R13/R12 version: 64 rows, 256 thr, 2 CTA/SM)
// ===========================================================================
#define WROW 200
#define AH_OFF 0
#define AL_OFF 25600
#define B_OFF  51200
#define BIAS_OFF 94208
#define SMEM_MLP 95744

__global__ __launch_bounds__(256, 2) void k_mlp_mma(const float* __restrict__ b1,
                                                    const float* __restrict__ b2) {
    extern __shared__ __align__(16) char smem[];
    const int t = threadIdx.x;
    const int wid = t >> 5, lane = t & 31;
    const int l4 = lane >> 2, qq = lane & 3;
    const int wm = wid & 1, wn = wid >> 1;
    const int n = blockIdx.y;
    const size_t pbase = (size_t)blockIdx.x * 64;
    const int cb = n * 96;
    const uint32_t sb = smem_u32(smem);

    // issue chunk 0 load immediately (layer0, part0, ck0)
    {
        const char* src = (const char*)(g_Wt + (size_t)n * 2 * 4 * CHUNK_ELEM);
        uint32_t dst = sb + B_OFF;
        for (int v = t; v < 1344; v += 256) cp16(dst + v * 16, src + v * 16);
        cp_commit();
    }

    float* sbias = (float*)(smem + BIAS_OFF);
    if (t < 96) {
        sbias[t]       = b1[cb + t];
        sbias[96 + t]  = b1[768 + cb + t];
        sbias[192 + t] = b2[cb + t];
        sbias[288 + t] = b2[768 + cb + t];
    }

    // ---- load + convert A tile (64 rows), float4 loads, batched MLP ----
    {
        const float* gYf = (const float*)g_Y;
        #pragma unroll
        for (int u = 0; u < 12; u++) {
            int idx = t + u * 256;               // 0..3071, pair-granularity
            int m = idx / 48, i2 = idx - m * 48; // i2: complex-pair 0..47
            float4 y2 = *(const float4*)(gYf + ((pbase + m) * CC + cb + 2 * i2) * 2);
            int k = 4 * i2;
            uint32_t h0 = pack_bf2(y2.x, y2.y);
            uint32_t h1 = pack_bf2(y2.z, y2.w);
            uint32_t lo0 = pack_bf2(lo_part(y2.x), lo_part(y2.y));
            uint32_t lo1 = pack_bf2(lo_part(y2.z), lo_part(y2.w));
            *(uint2*)(smem + AH_OFF + (m * WROW + k) * 2) = make_uint2(h0, h1);
            *(uint2*)(smem + AL_OFF + (m * WROW + k) * 2) = make_uint2(lo0, lo1);
        }
    }

    float c[2][6][4];
    #pragma unroll
    for (int mf = 0; mf < 2; mf++)
        #pragma unroll
        for (int nf = 0; nf < 6; nf++)
            #pragma unroll
            for (int e = 0; e < 4; e++) c[mf][nf][e] = 0.f;

    const int rb = 32 * wm;
    const int nbase = 48 * wn;

    // per-lane ldmatrix base addresses
    const int arow = rb + (lane & 7) + ((lane & 8) ? 8 : 0);
    const int acol = (lane & 16) ? 8 : 0;
    uint32_t aAddrH[2], aAddrL[2];
    #pragma unroll
    for (int mf = 0; mf < 2; mf++) {
        aAddrH[mf] = sb + AH_OFF + ((arow + 16 * mf) * WROW + acol) * 2;
        aAddrL[mf] = sb + AL_OFF + ((arow + 16 * mf) * WROW + acol) * 2;
    }
    const int brow = (lane & 7) + ((lane & 16) ? 8 : 0);
    const int bcol = (lane & 8) ? 8 : 0;
    uint32_t bAddr[3];
    #pragma unroll
    for (int bf = 0; bf < 3; bf++)
        bAddr[bf] = sb + B_OFF + ((nbase + 16 * bf + brow) * BROW + bcol) * 2;

    #pragma unroll 1
    for (int cid = 0; cid < 16; cid++) {
        cp_wait0();
        __syncthreads();
        if (cid < 15) {
            int nx = cid + 1;
            int l = nx >> 3, part = (nx >> 2) & 1, ck = nx & 3;
            const char* src = (const char*)(g_Wt +
                ((size_t)((l * 8 + n) * 2 + part) * 4 + ck) * CHUNK_ELEM);
            uint32_t dst = sb + B_OFF + (nx & 1) * 21504;
            #pragma unroll 1
            for (int v = t; v < 1344; v += 256) cp16(dst + v * 16, src + v * 16);
            cp_commit();
        }
        if (cid == 8) {
            // ---- epilogue 1: bias+GELU, rewrite A (hi/lo), reset accum ----
            #pragma unroll
            for (int mf = 0; mf < 2; mf++) {
                const int r0 = rb + 16 * mf + l4;
                #pragma unroll
                for (int nf = 0; nf < 6; nf++) {
                    const int n0 = nbase + 8 * nf + 2 * qq;
                    #pragma unroll
                    for (int e = 0; e < 4; e++) {
                        const int nc = n0 + (e & 1);
                        const int r = (e < 2) ? r0 : r0 + 8;
                        const int kk = (nc < 96) ? 2 * nc : 2 * (nc - 96) + 1;
                        float g = gelu_exact(c[mf][nf][e] + sbias[nc]);
                        *(__nv_bfloat16*)(smem + AH_OFF + (r * WROW + kk) * 2) =
                            __float2bfloat16(g);
                        *(__nv_bfloat16*)(smem + AL_OFF + (r * WROW + kk) * 2) =
                            __float2bfloat16(lo_part(g));
                        c[mf][nf][e] = 0.f;
                    }
                }
            }
            __syncthreads();
        }
        // ---- compute chunk cid ----
        {
            const int part = (cid >> 2) & 1;
            const int ck = cid & 3;
            const uint32_t boff = (cid & 1) * 21504;
            #pragma unroll
            for (int ksl = 0; ksl < 3; ksl++) {
                const int kl = ksl * 16;
                const uint32_t kg2 = (ck * 48 + kl) * 2;
                uint32_t ah[2][4], al[2][4];
                ldsm4(ah[0][0], ah[0][1], ah[0][2], ah[0][3], aAddrH[0] + kg2);
                ldsm4(ah[1][0], ah[1][1], ah[1][2], ah[1][3], aAddrH[1] + kg2);
                if (part == 0) {
                    ldsm4(al[0][0], al[0][1], al[0][2], al[0][3], aAddrL[0] + kg2);
                    ldsm4(al[1][0], al[1][1], al[1][2], al[1][3], aAddrL[1] + kg2);
                }
                #pragma unroll
                for (int bf = 0; bf < 3; bf++) {
                    uint32_t b0a, b1a, b0b, b1b;
                    ldsm4(b0a, b1a, b0b, b1b, bAddr[bf] + boff + kl * 2);
                    mma16816(c[0][2 * bf],     ah[0], b0a, b1a);
                    mma16816(c[1][2 * bf],     ah[1], b0a, b1a);
                    mma16816(c[0][2 * bf + 1], ah[0], b0b, b1b);
                    mma16816(c[1][2 * bf + 1], ah[1], b0b, b1b);
                    if (part == 0) {
                        mma16816(c[0][2 * bf],     al[0], b0a, b1a);
                        mma16816(c[1][2 * bf],     al[1], b0a, b1a);
                        mma16816(c[0][2 * bf + 1], al[0], b0b, b1b);
                        mma16816(c[1][2 * bf + 1], al[1], b0b, b1b);
                    }
                }
            }
        }
    }

    // ---- epilogue 2: bias + softshrink -> smem stage -> coalesced g_Y ----
    __syncthreads();                         // A regions now dead everywhere
    float* stage = (float*)(smem + AH_OFF);  // 64 rows x 192 floats (49KB)
    #pragma unroll
    for (int mf = 0; mf < 2; mf++) {
        const int r0 = rb + 16 * mf + l4;
        #pragma unroll
        for (int nf = 0; nf < 6; nf++) {
            const int n0 = nbase + 8 * nf + 2 * qq;
            #pragma unroll
            for (int e = 0; e < 4; e++) {
                const int nc = n0 + (e & 1);
                const int r = (e < 2) ? r0 : r0 + 8;
                float v = sshrink(c[mf][nf][e] + sbias[192 + nc]);
                const int cch = (nc < 96) ? nc : nc - 96;
                stage[r * 192 + 2 * cch + (nc >= 96)] = v;
            }
        }
    }
    __syncthreads();
    {
        float* gY = (float*)g_Y;
        #pragma unroll
        for (int u = 0; u < 12; u++) {
            int v = t + u * 256;
            int r = v / 48, q = v - r * 48;
            float4 val = ((const float4*)(stage + r * 192))[q];
            ((float4*)(gY + (pbase + r) * (CC * 2) + cb * 2))[q] = val;
        }
    }
}

// ===========================================================================
// K1: real FFT along W (four-step), 64 ch/CTA, launch_bounds(256,4).
// Writes transposed g_Y layout [B, kw, H, C]. ALSO performs weight prep
// (1 element/thread), hidden under the cp.async input load latency.
// ===========================================================================
__global__ __launch_bounds__(256, 4) void k_rfft_w(const float* __restrict__ x,
                                                   const float* __restrict__ w1,
                                                   const float* __restrict__ w2) {
    extern __shared__ __align__(16) float sm1[];
    float* sx = sm1;                         // 128 w * 64 c
    float* sg8 = sx + 8192;                  // 8 w0 * 64 c
    float2* tw = (float2*)(sg8 + 512);       // 128
    float2* tw16 = tw + 128;                 // 16

    const int t = threadIdx.x;
    const int bh = blockIdx.x;
    const int b = bh >> 7, h = bh & 127;
    const int cb = blockIdx.y * 64;
    const uint32_t sbx = smem_u32(sm1);

    const float* xp = x + (size_t)bh * WW * CC + cb;
    for (int v = t; v < 2048; v += 256) {          // 16B cp.async
        int w = v >> 4, c4 = v & 15;
        cp16(sbx + (w * 64 + c4 * 4) * 4, xp + (size_t)w * CC + c4 * 4);
    }
    cp_commit();

    // ---- folded weight prep: one element per thread, overlaps load ----
    {
        int gid = (blockIdx.y * 512 + blockIdx.x) * 256 + t;
        if (gid < NPREP) prep_one(gid, w1, w2);
    }

    if (t < 128) {
        double a = -2.0 * PI_D * (double)t / 128.0;
        tw[t] = make_float2((float)cos(a), (float)sin(a));
    }
    if (t < 16) {
        double a = -2.0 * PI_D * (double)t / 16.0;
        tw16[t] = make_float2((float)cos(a), (float)sin(a));
    }
    cp_wait0();
    __syncthreads();

    const int cl = t & 31;
    const int w0 = t >> 5;

    #pragma unroll
    for (int cc = 0; cc < 2; cc++) {
        const int ch = cl + 32 * cc;
        float xv[16];
        #pragma unroll
        for (int w1i = 0; w1i < 16; w1i++) xv[w1i] = sx[((w1i << 3) + w0) * 64 + ch];
        #pragma unroll
        for (int m = 0; m < 8; m++) {
            float2 E = make_float2(0.f, 0.f), O = make_float2(0.f, 0.f);
            int ph = 0; const int st = (2 * m) & 15;
            #pragma unroll
            for (int u = 0; u < 8; u++) {
                float2 tt = tw16[ph];
                E.x += xv[2 * u] * tt.x;     E.y += xv[2 * u] * tt.y;
                O.x += xv[2 * u + 1] * tt.x; O.y += xv[2 * u + 1] * tt.y;
                ph = (ph + st) & 15;
            }
            if (m == 0) sg8[w0 * 64 + ch] = E.x - O.x;
            float2 wm = tw16[m];
            float wOx = wm.x * O.x - wm.y * O.y;
            float wOy = wm.x * O.y + wm.y * O.x;
            sx[((m << 3) + w0) * 64 + ch]       = E.x + wOx;
            sx[(((m + 8) << 3) + w0) * 64 + ch] = E.y + wOy;
        }
    }
    __syncthreads();

    const int kq = w0;
    float2* yout = g_Y + ((size_t)b * WF * HH + h) * CC + cb;
    const size_t sk = (size_t)HH * CC;       // stride per kw
    const int jmax = (kq == 0) ? 9 : 8;
    for (int j = 0; j < jmax; j++) {
        const int k = kq + 8 * j;
        const int k0 = k & 15;
        const bool is8 = (k0 == 8);
        const int k0p = (k0 <= 8) ? k0 : 16 - k0;
        const float si = (k0 <= 8) ? 1.f : -1.f;
        #pragma unroll
        for (int cc = 0; cc < 2; cc++) {
            const int ch = cl + 32 * cc;
            float ax = 0.f, ay = 0.f;
            int ph = 0;
            #pragma unroll
            for (int p = 0; p < 8; p++) {
                float2 tt = tw[ph];
                float gre, gim;
                if (is8) { gre = sg8[p * 64 + ch]; gim = 0.f; }
                else {
                    gre = sx[((k0p << 3) + p) * 64 + ch];
                    gim = si * sx[(((k0p + 8) << 3) + p) * 64 + ch];
                }
                ax += gre * tt.x - gim * tt.y;
                ay += gre * tt.y + gim * tt.x;
                ph = (ph + k) & 127;
            }
            yout[(size_t)k * sk + ch] = make_float2(ax, ay);
        }
    }
}

// ===========================================================================
// K2/K4: complex FFT along H (four-step), IN PLACE, 64 ch/CTA,
// launch_bounds(256,3) for 3 CTAs/SM. (R13 version)
// ===========================================================================
__global__ __launch_bounds__(256, 3) void k_fft_h(float sgn, float scale) {
    extern __shared__ __align__(16) float sm2[];
    float2* sy = (float2*)sm2;
    float2* tw = sy + 8192;
    float2* tw16 = tw + 128;

    const int t = threadIdx.x;
    const int b  = blockIdx.x / WF;
    const int kw = blockIdx.x % WF;
    const int cb = blockIdx.y * 64;
    const size_t base = ((size_t)(b * WF + kw) * HH) * CC + cb;
    const uint32_t sbY = smem_u32(sm2);

    for (int v = t; v < 4096; v += 256) {          // 2 float2 per 16B op
        int h2 = v >> 5, c2 = (v & 31) * 2;
        cp16(sbY + (h2 * 64 + c2) * 8, (const char*)(g_Y + base + (size_t)h2 * CC + c2));
    }
    cp_commit();
    if (t < 128) {
        double a = sgn * 2.0 * PI_D * (double)t / 128.0;
        tw[t] = make_float2((float)cos(a), (float)sin(a));
    }
    if (t < 16) {
        double a = sgn * 2.0 * PI_D * (double)t / 16.0;
        tw16[t] = make_float2((float)cos(a), (float)sin(a));
    }
    cp_wait0();
    __syncthreads();

    const int cl = t & 31;
    const int h0 = t >> 5;

    #pragma unroll
    for (int cc = 0; cc < 2; cc++) {
        const int ch = cl + 32 * cc;
        float2 yv[16];
        #pragma unroll
        for (int h1 = 0; h1 < 16; h1++) yv[h1] = sy[((h1 << 3) + h0) * 64 + ch];
        #pragma unroll
        for (int m = 0; m < 8; m++) {
            float2 E = make_float2(0.f, 0.f), O = make_float2(0.f, 0.f);
            int ph = 0; const int st = (2 * m) & 15;
            #pragma unroll
            for (int u = 0; u < 8; u++) {
                float2 tt = tw16[ph];
                float2 a = yv[2 * u], bv = yv[2 * u + 1];
                E.x += a.x * tt.x - a.y * tt.y;   E.y += a.x * tt.y + a.y * tt.x;
                O.x += bv.x * tt.x - bv.y * tt.y; O.y += bv.x * tt.y + bv.y * tt.x;
                ph = (ph + st) & 15;
            }
            float2 wm = tw16[m];
            float wOx = wm.x * O.x - wm.y * O.y;
            float wOy = wm.x * O.y + wm.y * O.x;
            sy[((m << 3) + h0) * 64 + ch]       = make_float2(E.x + wOx, E.y + wOy);
            sy[(((m + 8) << 3) + h0) * 64 + ch] = make_float2(E.x - wOx, E.y - wOy);
        }
    }
    __syncthreads();

    const int kq = h0;
    #pragma unroll 2
    for (int j = 0; j < 8; j++) {
        const int k = kq + 8 * j;
        const int k0 = k & 15;
        #pragma unroll
        for (int cc = 0; cc < 2; cc++) {
            const int ch = cl + 32 * cc;
            float Ex = 0.f, Ey = 0.f, Ox = 0.f, Oy = 0.f;
            int ph = 0;
            #pragma unroll
            for (int p = 0; p < 8; p++) {
                float2 tt = tw[ph];
                float2 g = sy[((k0 << 3) + p) * 64 + ch];
                float rx = g.x * tt.x - g.y * tt.y;
                float ry = g.x * tt.y + g.y * tt.x;
                if ((p & 1) == 0) { Ex += rx; Ey += ry; }
                else              { Ox += rx; Oy += ry; }
                ph = (ph + k) & 127;
            }
            g_Y[base + (size_t)k * CC + ch] =
                make_float2((Ex + Ox) * scale, (Ey + Oy) * scale);
            g_Y[base + (size_t)(k + 64) * CC + ch] =
                make_float2((Ex - Ox) * scale, (Ey - Oy) * scale);
        }
    }
}

// ===========================================================================
// K5: inverse real FFT along W (four-step), 64 ch/CTA, launch_bounds(256,3).
// (R13 version)
// ===========================================================================
__global__ __launch_bounds__(256, 3) void k_irfft_w(float* __restrict__ out) {
    extern __shared__ __align__(16) float sm5[];
    float2* sz = (float2*)sm5;
    float2* tw = sz + 8192;
    float2* tw16 = tw + 128;

    const int t = threadIdx.x;
    const int bh = blockIdx.x;
    const int b = bh >> 7, h = bh & 127;
    const int cb = blockIdx.y * 64;
    const size_t base = ((size_t)b * WF * HH + h) * CC + cb;
    const size_t sk = (size_t)HH * CC;
    const uint32_t sbZ = smem_u32(sm5);

    for (int v = t; v < 2080; v += 256) {          // rows 0..64, 2 float2/op
        int k = v >> 5, c2 = (v & 31) * 2;
        cp16(sbZ + (k * 64 + c2) * 8, (const char*)(g_Y + base + (size_t)k * sk + c2));
    }
    cp_commit();
    if (t < 128) {
        double a = 2.0 * PI_D * (double)t / 128.0;
        tw[t] = make_float2((float)cos(a), (float)sin(a));
    }
    if (t < 16) {
        double a = 2.0 * PI_D * (double)t / 16.0;
        tw16[t] = make_float2((float)cos(a), (float)sin(a));
    }
    cp_wait0();
    __syncthreads();
    // mirror rows 65..127 from smem (conjugate)
    for (int idx = t; idx < 63 * 64; idx += 256) {
        int k = 65 + (idx >> 6), c = idx & 63;
        float2 v2 = sz[((128 - k) << 6) + c];
        sz[(k << 6) + c] = make_float2(v2.x, -v2.y);
    }
    __syncthreads();

    const int cl = t & 31;
    const int k0c = t >> 5;

    #pragma unroll
    for (int cc = 0; cc < 2; cc++) {
        const int ch = cl + 32 * cc;
        float2 yv[16];
        #pragma unroll
        for (int k1 = 0; k1 < 16; k1++) yv[k1] = sz[((k1 << 3) + k0c) * 64 + ch];
        #pragma unroll
        for (int m = 0; m < 8; m++) {
            float2 E = make_float2(0.f, 0.f), O = make_float2(0.f, 0.f);
            int ph = 0; const int st = (2 * m) & 15;
            #pragma unroll
            for (int u = 0; u < 8; u++) {
                float2 tt = tw16[ph];
                float2 a = yv[2 * u], bv = yv[2 * u + 1];
                E.x += a.x * tt.x - a.y * tt.y;   E.y += a.x * tt.y + a.y * tt.x;
                O.x += bv.x * tt.x - bv.y * tt.y; O.y += bv.x * tt.y + bv.y * tt.x;
                ph = (ph + st) & 15;
            }
            float2 wm = tw16[m];
            float wOx = wm.x * O.x - wm.y * O.y;
            float wOy = wm.x * O.y + wm.y * O.x;
            sz[((m << 3) + k0c) * 64 + ch]       = make_float2(E.x + wOx, E.y + wOy);
            sz[(((m + 8) << 3) + k0c) * 64 + ch] = make_float2(E.x - wOx, E.y - wOy);
        }
    }
    __syncthreads();

    const int wq = k0c;
    const float inv = 1.0f / 128.0f;
    float* op = out + (size_t)bh * WW * CC + cb;
    #pragma unroll 2
    for (int j = 0; j < 8; j++) {
        const int w = wq + 8 * j;
        const int m = w & 15;
        #pragma unroll
        for (int cc = 0; cc < 2; cc++) {
            const int ch = cl + 32 * cc;
            float e = 0.f, o = 0.f;
            int ph = 0;
            #pragma unroll
            for (int p = 0; p < 8; p++) {
                float2 tt = tw[ph];
                float2 g = sz[((m << 3) + p) * 64 + ch];
                float re = g.x * tt.x - g.y * tt.y;
                if ((p & 1) == 0) e += re; else o += re;
                ph = (ph + w) & 127;
            }
            op[(size_t)w * CC + ch]        = (e + o) * inv;
            op[(size_t)(w + 64) * CC + ch] = (e - o) * inv;
        }
    }
}

// ---------------------------------------------------------------------------
extern "C" void kernel_launch(void* const* d_in, const int* in_sizes, int n_in,
                              void* d_out, int out_size) {
    const float* x  = (const float*)d_in[0];
    const float* w1 = (const float*)d_in[1];
    const float* b1 = (const float*)d_in[2];
    const float* w2 = (const float*)d_in[3];
    const float* b2 = (const float*)d_in[4];
    float* out = (float*)d_out;

    const int smem_rfft  = 8192 * 4 + 512 * 4 + 128 * 8 + 16 * 8;
    const int smem_ffth  = 8192 * 8 + 128 * 8 + 16 * 8;
    const int smem_irfft = 8192 * 8 + 128 * 8 + 16 * 8;
    cudaFuncSetAttribute(k_rfft_w,  cudaFuncAttributeMaxDynamicSharedMemorySize, smem_rfft);
    cudaFuncSetAttribute(k_fft_h,   cudaFuncAttributeMaxDynamicSharedMemorySize, smem_ffth);
    cudaFuncSetAttribute(k_mlp_mma, cudaFuncAttributeMaxDynamicSharedMemorySize, SMEM_MLP);
    cudaFuncSetAttribute(k_irfft_w, cudaFuncAttributeMaxDynamicSharedMemorySize, smem_irfft);

    dim3 g1(BB * HH, CC / 64);           // (512, 12)
    k_rfft_w<<<g1, 256, smem_rfft>>>(x, w1, w2);   // prep folded in

    dim3 g2(BB * WF, CC / 64);           // (260, 12)
    k_fft_h<<<g2, 256, smem_ffth>>>(-1.0f, 1.0f / 128.0f);

    dim3 g3(520, NB);                    // 33280/64 = 520 m-tiles
    k_mlp_mma<<<g3, 256, SMEM_MLP>>>(b1, b2);

    k_fft_h<<<g2, 256, smem_ffth>>>(+1.0f, 1.0f);

    k_irfft_w<<<g1, 256, smem_irfft>>>(out);
}

// round 17
// speedup vs baseline: 1.0971x; 1.0519x over previous
#include <cuda_runtime.h>
#include <cuda_bf16.h>
#include <math.h>
#include <stdint.h>

#define BB 4
#define HH 128
#define WW 128
#define CC 768
#define WF 65            // WW/2 + 1
#define NB 8
#define PI_D 3.14159265358979323846

// Spectrum scratch, interleaved complex, layout [B, kw, H, C] (~204MB)
#define NSPEC (BB * WF * HH * CC)
__device__ float2 g_Y[NSPEC];

// Chunk-major bf16 weight images:
// [2 layers][8 n][2 parts(hi/lo)][4 chunks][192 rows][56 cols(48 used)]
#define BROW 56
#define CHUNK_ELEM (192 * BROW)           // 10752 elems = 21504 B
__device__ __align__(16) __nv_bfloat16 g_Wt[2 * 8 * 2 * 4 * CHUNK_ELEM];

__device__ __forceinline__ float gelu_exact(float x) {
    return 0.5f * x * (1.0f + erff(x * 0.7071067811865476f));
}
__device__ __forceinline__ float sshrink(float v) {
    float a = fabsf(v) - 0.01f;
    return a > 0.0f ? copysignf(a, v) : 0.0f;
}
__device__ __forceinline__ uint32_t pack_bf2(float a, float b) {
    __nv_bfloat162 p = make_bfloat162(__float2bfloat16(a), __float2bfloat16(b));
    return *(uint32_t*)&p;
}
__device__ __forceinline__ float lo_part(float v) {
    return v - __bfloat162float(__float2bfloat16(v));
}
__device__ __forceinline__ uint32_t smem_u32(const void* p) {
    uint32_t a;
    asm("{ .reg .u64 t; cvta.to.shared.u64 t, %1; cvt.u32.u64 %0, t; }"
        : "=r"(a) : "l"(p));
    return a;
}
__device__ __forceinline__ void cp16(uint32_t dst, const void* src) {
    asm volatile("cp.async.cg.shared.global [%0], [%1], 16;" :: "r"(dst), "l"(src));
}
__device__ __forceinline__ void cp_commit() {
    asm volatile("cp.async.commit_group;" ::: "memory");
}
__device__ __forceinline__ void cp_wait0() {
    asm volatile("cp.async.wait_group 0;" ::: "memory");
}
__device__ __forceinline__ void ldsm4(uint32_t& r0, uint32_t& r1,
                                      uint32_t& r2, uint32_t& r3, uint32_t addr) {
    asm volatile("ldmatrix.sync.aligned.m8n8.x4.shared.b16 {%0,%1,%2,%3}, [%4];"
                 : "=r"(r0), "=r"(r1), "=r"(r2), "=r"(r3) : "r"(addr));
}

// m16n8k16 row.col bf16 -> f32 accumulate
__device__ __forceinline__ void mma16816(float* c, const uint32_t* a,
                                         uint32_t b0, uint32_t b1) {
    asm volatile(
        "mma.sync.aligned.m16n8k16.row.col.f32.bf16.bf16.f32 "
        "{%0,%1,%2,%3}, {%4,%5,%6,%7}, {%8,%9}, {%0,%1,%2,%3};"
        : "+f"(c[0]), "+f"(c[1]), "+f"(c[2]), "+f"(c[3])
        : "r"(a[0]), "r"(a[1]), "r"(a[2]), "r"(a[3]), "r"(b0), "r"(b1));
}

// ===========================================================================
// K0: weight prep -> chunk-major layout.
// ===========================================================================
__global__ __launch_bounds__(256) void k_prep(const float* __restrict__ w1,
                                              const float* __restrict__ w2) {
    int gid = blockIdx.x * 256 + threadIdx.x;
    if (gid >= 2 * 8 * 2 * 4 * CHUNK_ELEM) return;
    int kc = gid % BROW;
    int nn = (gid / BROW) % 192;
    int ck = (gid / CHUNK_ELEM) % 4;
    int part = (gid / (CHUNK_ELEM * 4)) % 2;
    int n = (gid / (CHUNK_ELEM * 8)) % 8;
    int l = gid / (CHUNK_ELEM * 64);
    float v = 0.f;
    if (kc < 48) {
        int k = ck * 48 + kc;
        const float* W = l ? w2 : w1;
        int i = k >> 1, odd = k & 1;
        if (nn < 96) {
            v = odd ? -W[73728 + n * 9216 + i * 96 + nn]
                    :  W[n * 9216 + i * 96 + nn];
        } else {
            int o = nn - 96;
            v = odd ? W[n * 9216 + i * 96 + o]
                    : W[73728 + n * 9216 + i * 96 + o];
        }
    }
    if (part) v = lo_part(v);
    g_Wt[gid] = __float2bfloat16(v);
}

// ===========================================================================
// K3: warp-MMA complex MLP, 3-term bf16 hi/lo (AhBh + AlBh + AhBl).
// 64 rows/CTA, 256 thr, 2 CTAs/SM, 16 chunks double-buffered cp.async.
// Epilogue-2 stage padded to 196-float rows (bank-conflict-free).
// ===========================================================================
#define WROW 200
#define STGROW 196
#define AH_OFF 0
#define AL_OFF 25600
#define B_OFF  51200
#define BIAS_OFF 94208
#define SMEM_MLP 95744

__global__ __launch_bounds__(256, 2) void k_mlp_mma(const float* __restrict__ b1,
                                                    const float* __restrict__ b2) {
    extern __shared__ __align__(16) char smem[];
    const int t = threadIdx.x;
    const int wid = t >> 5, lane = t & 31;
    const int l4 = lane >> 2, qq = lane & 3;
    const int wm = wid & 1, wn = wid >> 1;
    const int n = blockIdx.y;
    const size_t pbase = (size_t)blockIdx.x * 64;
    const int cb = n * 96;
    const uint32_t sb = smem_u32(smem);

    // issue chunk 0 load immediately (layer0, part0, ck0)
    {
        const char* src = (const char*)(g_Wt + (size_t)n * 2 * 4 * CHUNK_ELEM);
        uint32_t dst = sb + B_OFF;
        for (int v = t; v < 1344; v += 256) cp16(dst + v * 16, src + v * 16);
        cp_commit();
    }

    float* sbias = (float*)(smem + BIAS_OFF);
    if (t < 96) {
        sbias[t]       = b1[cb + t];
        sbias[96 + t]  = b1[768 + cb + t];
        sbias[192 + t] = b2[cb + t];
        sbias[288 + t] = b2[768 + cb + t];
    }

    // ---- load + convert A tile (64 rows), float4 loads, batched MLP ----
    {
        const float* gYf = (const float*)g_Y;
        #pragma unroll
        for (int u = 0; u < 12; u++) {
            int idx = t + u * 256;               // 0..3071, pair-granularity
            int m = idx / 48, i2 = idx - m * 48; // i2: complex-pair 0..47
            float4 y2 = *(const float4*)(gYf + ((pbase + m) * CC + cb + 2 * i2) * 2);
            int k = 4 * i2;
            uint32_t h0 = pack_bf2(y2.x, y2.y);
            uint32_t h1 = pack_bf2(y2.z, y2.w);
            uint32_t lo0 = pack_bf2(lo_part(y2.x), lo_part(y2.y));
            uint32_t lo1 = pack_bf2(lo_part(y2.z), lo_part(y2.w));
            *(uint2*)(smem + AH_OFF + (m * WROW + k) * 2) = make_uint2(h0, h1);
            *(uint2*)(smem + AL_OFF + (m * WROW + k) * 2) = make_uint2(lo0, lo1);
        }
    }

    float c[2][6][4];
    #pragma unroll
    for (int mf = 0; mf < 2; mf++)
        #pragma unroll
        for (int nf = 0; nf < 6; nf++)
            #pragma unroll
            for (int e = 0; e < 4; e++) c[mf][nf][e] = 0.f;

    const int rb = 32 * wm;
    const int nbase = 48 * wn;

    // per-lane ldmatrix base addresses
    const int arow = rb + (lane & 7) + ((lane & 8) ? 8 : 0);
    const int acol = (lane & 16) ? 8 : 0;
    uint32_t aAddrH[2], aAddrL[2];
    #pragma unroll
    for (int mf = 0; mf < 2; mf++) {
        aAddrH[mf] = sb + AH_OFF + ((arow + 16 * mf) * WROW + acol) * 2;
        aAddrL[mf] = sb + AL_OFF + ((arow + 16 * mf) * WROW + acol) * 2;
    }
    const int brow = (lane & 7) + ((lane & 16) ? 8 : 0);
    const int bcol = (lane & 8) ? 8 : 0;
    uint32_t bAddr[3];
    #pragma unroll
    for (int bf = 0; bf < 3; bf++)
        bAddr[bf] = sb + B_OFF + ((nbase + 16 * bf + brow) * BROW + bcol) * 2;

    #pragma unroll 1
    for (int cid = 0; cid < 16; cid++) {
        cp_wait0();
        __syncthreads();
        if (cid < 15) {
            int nx = cid + 1;
            int l = nx >> 3, part = (nx >> 2) & 1, ck = nx & 3;
            const char* src = (const char*)(g_Wt +
                ((size_t)((l * 8 + n) * 2 + part) * 4 + ck) * CHUNK_ELEM);
            uint32_t dst = sb + B_OFF + (nx & 1) * 21504;
            #pragma unroll 1
            for (int v = t; v < 1344; v += 256) cp16(dst + v * 16, src + v * 16);
            cp_commit();
        }
        if (cid == 8) {
            // ---- epilogue 1: bias+GELU, rewrite A (hi/lo), reset accum ----
            #pragma unroll
            for (int mf = 0; mf < 2; mf++) {
                const int r0 = rb + 16 * mf + l4;
                #pragma unroll
                for (int nf = 0; nf < 6; nf++) {
                    const int n0 = nbase + 8 * nf + 2 * qq;
                    #pragma unroll
                    for (int e = 0; e < 4; e++) {
                        const int nc = n0 + (e & 1);
                        const int r = (e < 2) ? r0 : r0 + 8;
                        const int kk = (nc < 96) ? 2 * nc : 2 * (nc - 96) + 1;
                        float g = gelu_exact(c[mf][nf][e] + sbias[nc]);
                        *(__nv_bfloat16*)(smem + AH_OFF + (r * WROW + kk) * 2) =
                            __float2bfloat16(g);
                        *(__nv_bfloat16*)(smem + AL_OFF + (r * WROW + kk) * 2) =
                            __float2bfloat16(lo_part(g));
                        c[mf][nf][e] = 0.f;
                    }
                }
            }
            __syncthreads();
        }
        // ---- compute chunk cid ----
        {
            const int part = (cid >> 2) & 1;
            const int ck = cid & 3;
            const uint32_t boff = (cid & 1) * 21504;
            #pragma unroll
            for (int ksl = 0; ksl < 3; ksl++) {
                const int kl = ksl * 16;
                const uint32_t kg2 = (ck * 48 + kl) * 2;
                uint32_t ah[2][4], al[2][4];
                ldsm4(ah[0][0], ah[0][1], ah[0][2], ah[0][3], aAddrH[0] + kg2);
                ldsm4(ah[1][0], ah[1][1], ah[1][2], ah[1][3], aAddrH[1] + kg2);
                if (part == 0) {
                    ldsm4(al[0][0], al[0][1], al[0][2], al[0][3], aAddrL[0] + kg2);
                    ldsm4(al[1][0], al[1][1], al[1][2], al[1][3], aAddrL[1] + kg2);
                }
                #pragma unroll
                for (int bf = 0; bf < 3; bf++) {
                    uint32_t b0a, b1a, b0b, b1b;
                    ldsm4(b0a, b1a, b0b, b1b, bAddr[bf] + boff + kl * 2);
                    mma16816(c[0][2 * bf],     ah[0], b0a, b1a);
                    mma16816(c[1][2 * bf],     ah[1], b0a, b1a);
                    mma16816(c[0][2 * bf + 1], ah[0], b0b, b1b);
                    mma16816(c[1][2 * bf + 1], ah[1], b0b, b1b);
                    if (part == 0) {
                        mma16816(c[0][2 * bf],     al[0], b0a, b1a);
                        mma16816(c[1][2 * bf],     al[1], b0a, b1a);
                        mma16816(c[0][2 * bf + 1], al[0], b0b, b1b);
                        mma16816(c[1][2 * bf + 1], al[1], b0b, b1b);
                    }
                }
            }
        }
    }

    // ---- epilogue 2: bias + softshrink -> padded smem stage -> g_Y ----
    __syncthreads();                         // A regions now dead everywhere
    float* stage = (float*)(smem + AH_OFF);  // 64 rows x 196 floats (50.2KB)
    #pragma unroll
    for (int mf = 0; mf < 2; mf++) {
        const int r0 = rb + 16 * mf + l4;
        #pragma unroll
        for (int nf = 0; nf < 6; nf++) {
            const int n0 = nbase + 8 * nf + 2 * qq;
            #pragma unroll
            for (int e = 0; e < 4; e++) {
                const int nc = n0 + (e & 1);
                const int r = (e < 2) ? r0 : r0 + 8;
                float v = sshrink(c[mf][nf][e] + sbias[192 + nc]);
                const int cch = (nc < 96) ? nc : nc - 96;
                stage[r * STGROW + 2 * cch + (nc >= 96)] = v;
            }
        }
    }
    __syncthreads();
    {
        float* gY = (float*)g_Y;
        #pragma unroll
        for (int u = 0; u < 12; u++) {
            int v = t + u * 256;
            int r = v / 48, q = v - r * 48;
            float4 val = ((const float4*)(stage + r * STGROW))[q];
            ((float4*)(gY + (pbase + r) * (CC * 2) + cb * 2))[q] = val;
        }
    }
}

// ===========================================================================
// K1: real FFT along W (four-step), 64 ch/CTA, launch_bounds(256,4).
// Writes transposed g_Y layout [B, kw, H, C].
// ===========================================================================
__global__ __launch_bounds__(256, 4) void k_rfft_w(const float* __restrict__ x) {
    extern __shared__ __align__(16) float sm1[];
    float* sx = sm1;                         // 128 w * 64 c
    float* sg8 = sx + 8192;                  // 8 w0 * 64 c
    float2* tw = (float2*)(sg8 + 512);       // 128
    float2* tw16 = tw + 128;                 // 16

    const int t = threadIdx.x;
    const int bh = blockIdx.x;
    const int b = bh >> 7, h = bh & 127;
    const int cb = blockIdx.y * 64;
    const uint32_t sbx = smem_u32(sm1);

    const float* xp = x + (size_t)bh * WW * CC + cb;
    for (int v = t; v < 2048; v += 256) {          // 16B cp.async
        int w = v >> 4, c4 = v & 15;
        cp16(sbx + (w * 64 + c4 * 4) * 4, xp + (size_t)w * CC + c4 * 4);
    }
    cp_commit();
    if (t < 128) {
        double a = -2.0 * PI_D * (double)t / 128.0;
        tw[t] = make_float2((float)cos(a), (float)sin(a));
    }
    if (t < 16) {
        double a = -2.0 * PI_D * (double)t / 16.0;
        tw16[t] = make_float2((float)cos(a), (float)sin(a));
    }
    cp_wait0();
    __syncthreads();

    const int cl = t & 31;
    const int w0 = t >> 5;

    #pragma unroll
    for (int cc = 0; cc < 2; cc++) {
        const int ch = cl + 32 * cc;
        float xv[16];
        #pragma unroll
        for (int w1 = 0; w1 < 16; w1++) xv[w1] = sx[((w1 << 3) + w0) * 64 + ch];
        #pragma unroll
        for (int m = 0; m < 8; m++) {
            float2 E = make_float2(0.f, 0.f), O = make_float2(0.f, 0.f);
            int ph = 0; const int st = (2 * m) & 15;
            #pragma unroll
            for (int u = 0; u < 8; u++) {
                float2 tt = tw16[ph];
                E.x += xv[2 * u] * tt.x;     E.y += xv[2 * u] * tt.y;
                O.x += xv[2 * u + 1] * tt.x; O.y += xv[2 * u + 1] * tt.y;
                ph = (ph + st) & 15;
            }
            if (m == 0) sg8[w0 * 64 + ch] = E.x - O.x;
            float2 wm = tw16[m];
            float wOx = wm.x * O.x - wm.y * O.y;
            float wOy = wm.x * O.y + wm.y * O.x;
            sx[((m << 3) + w0) * 64 + ch]       = E.x + wOx;
            sx[(((m + 8) << 3) + w0) * 64 + ch] = E.y + wOy;
        }
    }
    __syncthreads();

    const int kq = w0;
    float2* yout = g_Y + ((size_t)b * WF * HH + h) * CC + cb;
    const size_t sk = (size_t)HH * CC;       // stride per kw
    const int jmax = (kq == 0) ? 9 : 8;
    for (int j = 0; j < jmax; j++) {
        const int k = kq + 8 * j;
        const int k0 = k & 15;
        const bool is8 = (k0 == 8);
        const int k0p = (k0 <= 8) ? k0 : 16 - k0;
        const float si = (k0 <= 8) ? 1.f : -1.f;
        #pragma unroll
        for (int cc = 0; cc < 2; cc++) {
            const int ch = cl + 32 * cc;
            float ax = 0.f, ay = 0.f;
            int ph = 0;
            #pragma unroll
            for (int p = 0; p < 8; p++) {
                float2 tt = tw[ph];
                float gre, gim;
                if (is8) { gre = sg8[p * 64 + ch]; gim = 0.f; }
                else {
                    gre = sx[((k0p << 3) + p) * 64 + ch];
                    gim = si * sx[(((k0p + 8) << 3) + p) * 64 + ch];
                }
                ax += gre * tt.x - gim * tt.y;
                ay += gre * tt.y + gim * tt.x;
                ph = (ph + k) & 127;
            }
            yout[(size_t)k * sk + ch] = make_float2(ax, ay);
        }
    }
}

// ===========================================================================
// K2/K4: complex FFT along H (four-step), IN PLACE, 64 ch/CTA,
// launch_bounds(256,3) for 3 CTAs/SM.
// ===========================================================================
__global__ __launch_bounds__(256, 3) void k_fft_h(float sgn, float scale) {
    extern __shared__ __align__(16) float sm2[];
    float2* sy = (float2*)sm2;
    float2* tw = sy + 8192;
    float2* tw16 = tw + 128;

    const int t = threadIdx.x;
    const int b  = blockIdx.x / WF;
    const int kw = blockIdx.x % WF;
    const int cb = blockIdx.y * 64;
    const size_t base = ((size_t)(b * WF + kw) * HH) * CC + cb;
    const uint32_t sbY = smem_u32(sm2);

    for (int v = t; v < 4096; v += 256) {          // 2 float2 per 16B op
        int h2 = v >> 5, c2 = (v & 31) * 2;
        cp16(sbY + (h2 * 64 + c2) * 8, (const char*)(g_Y + base + (size_t)h2 * CC + c2));
    }
    cp_commit();
    if (t < 128) {
        double a = sgn * 2.0 * PI_D * (double)t / 128.0;
        tw[t] = make_float2((float)cos(a), (float)sin(a));
    }
    if (t < 16) {
        double a = sgn * 2.0 * PI_D * (double)t / 16.0;
        tw16[t] = make_float2((float)cos(a), (float)sin(a));
    }
    cp_wait0();
    __syncthreads();

    const int cl = t & 31;
    const int h0 = t >> 5;

    #pragma unroll
    for (int cc = 0; cc < 2; cc++) {
        const int ch = cl + 32 * cc;
        float2 yv[16];
        #pragma unroll
        for (int h1 = 0; h1 < 16; h1++) yv[h1] = sy[((h1 << 3) + h0) * 64 + ch];
        #pragma unroll
        for (int m = 0; m < 8; m++) {
            float2 E = make_float2(0.f, 0.f), O = make_float2(0.f, 0.f);
            int ph = 0; const int st = (2 * m) & 15;
            #pragma unroll
            for (int u = 0; u < 8; u++) {
                float2 tt = tw16[ph];
                float2 a = yv[2 * u], bv = yv[2 * u + 1];
                E.x += a.x * tt.x - a.y * tt.y;   E.y += a.x * tt.y + a.y * tt.x;
                O.x += bv.x * tt.x - bv.y * tt.y; O.y += bv.x * tt.y + bv.y * tt.x;
                ph = (ph + st) & 15;
            }
            float2 wm = tw16[m];
            float wOx = wm.x * O.x - wm.y * O.y;
            float wOy = wm.x * O.y + wm.y * O.x;
            sy[((m << 3) + h0) * 64 + ch]       = make_float2(E.x + wOx, E.y + wOy);
            sy[(((m + 8) << 3) + h0) * 64 + ch] = make_float2(E.x - wOx, E.y - wOy);
        }
    }
    __syncthreads();

    const int kq = h0;
    #pragma unroll 2
    for (int j = 0; j < 8; j++) {
        const int k = kq + 8 * j;
        const int k0 = k & 15;
        #pragma unroll
        for (int cc = 0; cc < 2; cc++) {
            const int ch = cl + 32 * cc;
            float Ex = 0.f, Ey = 0.f, Ox = 0.f, Oy = 0.f;
            int ph = 0;
            #pragma unroll
            for (int p = 0; p < 8; p++) {
                float2 tt = tw[ph];
                float2 g = sy[((k0 << 3) + p) * 64 + ch];
                float rx = g.x * tt.x - g.y * tt.y;
                float ry = g.x * tt.y + g.y * tt.x;
                if ((p & 1) == 0) { Ex += rx; Ey += ry; }
                else              { Ox += rx; Oy += ry; }
                ph = (ph + k) & 127;
            }
            g_Y[base + (size_t)k * CC + ch] =
                make_float2((Ex + Ox) * scale, (Ey + Oy) * scale);
            g_Y[base + (size_t)(k + 64) * CC + ch] =
                make_float2((Ex - Ox) * scale, (Ey - Oy) * scale);
        }
    }
}

// ===========================================================================
// K5: inverse real FFT along W (four-step), 64 ch/CTA, launch_bounds(256,3).
// ===========================================================================
__global__ __launch_bounds__(256, 3) void k_irfft_w(float* __restrict__ out) {
    extern __shared__ __align__(16) float sm5[];
    float2* sz = (float2*)sm5;
    float2* tw = sz + 8192;
    float2* tw16 = tw + 128;

    const int t = threadIdx.x;
    const int bh = blockIdx.x;
    const int b = bh >> 7, h = bh & 127;
    const int cb = blockIdx.y * 64;
    const size_t base = ((size_t)b * WF * HH + h) * CC + cb;
    const size_t sk = (size_t)HH * CC;
    const uint32_t sbZ = smem_u32(sm5);

    for (int v = t; v < 2080; v += 256) {          // rows 0..64, 2 float2/op
        int k = v >> 5, c2 = (v & 31) * 2;
        cp16(sbZ + (k * 64 + c2) * 8, (const char*)(g_Y + base + (size_t)k * sk + c2));
    }
    cp_commit();
    if (t < 128) {
        double a = 2.0 * PI_D * (double)t / 128.0;
        tw[t] = make_float2((float)cos(a), (float)sin(a));
    }
    if (t < 16) {
        double a = 2.0 * PI_D * (double)t / 16.0;
        tw16[t] = make_float2((float)cos(a), (float)sin(a));
    }
    cp_wait0();
    __syncthreads();
    // mirror rows 65..127 from smem (conjugate)
    for (int idx = t; idx < 63 * 64; idx += 256) {
        int k = 65 + (idx >> 6), c = idx & 63;
        float2 v2 = sz[((128 - k) << 6) + c];
        sz[(k << 6) + c] = make_float2(v2.x, -v2.y);
    }
    __syncthreads();

    const int cl = t & 31;
    const int k0c = t >> 5;

    #pragma unroll
    for (int cc = 0; cc < 2; cc++) {
        const int ch = cl + 32 * cc;
        float2 yv[16];
        #pragma unroll
        for (int k1 = 0; k1 < 16; k1++) yv[k1] = sz[((k1 << 3) + k0c) * 64 + ch];
        #pragma unroll
        for (int m = 0; m < 8; m++) {
            float2 E = make_float2(0.f, 0.f), O = make_float2(0.f, 0.f);
            int ph = 0; const int st = (2 * m) & 15;
            #pragma unroll
            for (int u = 0; u < 8; u++) {
                float2 tt = tw16[ph];
                float2 a = yv[2 * u], bv = yv[2 * u + 1];
                E.x += a.x * tt.x - a.y * tt.y;   E.y += a.x * tt.y + a.y * tt.x;
                O.x += bv.x * tt.x - bv.y * tt.y; O.y += bv.x * tt.y + bv.y * tt.x;
                ph = (ph + st) & 15;
            }
            float2 wm = tw16[m];
            float wOx = wm.x * O.x - wm.y * O.y;
            float wOy = wm.x * O.y + wm.y * O.x;
            sz[((m << 3) + k0c) * 64 + ch]       = make_float2(E.x + wOx, E.y + wOy);
            sz[(((m + 8) << 3) + k0c) * 64 + ch] = make_float2(E.x - wOx, E.y - wOy);
        }
    }
    __syncthreads();

    const int wq = k0c;
    const float inv = 1.0f / 128.0f;
    float* op = out + (size_t)bh * WW * CC + cb;
    #pragma unroll 2
    for (int j = 0; j < 8; j++) {
        const int w = wq + 8 * j;
        const int m = w & 15;
        #pragma unroll
        for (int cc = 0; cc < 2; cc++) {
            const int ch = cl + 32 * cc;
            float e = 0.f, o = 0.f;
            int ph = 0;
            #pragma unroll
            for (int p = 0; p < 8; p++) {
                float2 tt = tw[ph];
                float2 g = sz[((m << 3) + p) * 64 + ch];
                float re = g.x * tt.x - g.y * tt.y;
                if ((p & 1) == 0) e += re; else o += re;
                ph = (ph + w) & 127;
            }
            op[(size_t)w * CC + ch]        = (e + o) * inv;
            op[(size_t)(w + 64) * CC + ch] = (e - o) * inv;
        }
    }
}

// ---------------------------------------------------------------------------
extern "C" void kernel_launch(void* const* d_in, const int* in_sizes, int n_in,
                              void* d_out, int out_size) {
    const float* x  = (const float*)d_in[0];
    const float* w1 = (const float*)d_in[1];
    const float* b1 = (const float*)d_in[2];
    const float* w2 = (const float*)d_in[3];
    const float* b2 = (const float*)d_in[4];
    float* out = (float*)d_out;

    const int smem_rfft  = 8192 * 4 + 512 * 4 + 128 * 8 + 16 * 8;
    const int smem_ffth  = 8192 * 8 + 128 * 8 + 16 * 8;
    const int smem_irfft = 8192 * 8 + 128 * 8 + 16 * 8;
    cudaFuncSetAttribute(k_rfft_w,  cudaFuncAttributeMaxDynamicSharedMemorySize, smem_rfft);
    cudaFuncSetAttribute(k_fft_h,   cudaFuncAttributeMaxDynamicSharedMemorySize, smem_ffth);
    cudaFuncSetAttribute(k_mlp_mma, cudaFuncAttributeMaxDynamicSharedMemorySize, SMEM_MLP);
    cudaFuncSetAttribute(k_irfft_w, cudaFuncAttributeMaxDynamicSharedMemorySize, smem_irfft);

    k_prep<<<5376, 256>>>(w1, w2);

    dim3 g1(BB * HH, CC / 64);           // (512, 12)
    k_rfft_w<<<g1, 256, smem_rfft>>>(x);

    dim3 g2(BB * WF, CC / 64);           // (260, 12)
    k_fft_h<<<g2, 256, smem_ffth>>>(-1.0f, 1.0f / 128.0f);

    dim3 g3(520, NB);                    // 33280/64 = 520 m-tiles
    k_mlp_mma<<<g3, 256, SMEM_MLP>>>(b1, b2);

    k_fft_h<<<g2, 256, smem_ffth>>>(+1.0f, 1.0f);

    k_irfft_w<<<g1, 256, smem_irfft>>>(out);
}